// round 3
// baseline (speedup 1.0000x reference)
#include <cuda_runtime.h>

#define N_NODES 100000
#define E_MAX   3200000
#define F_INN   300
#define HID     16
#define C_OUT   10
#define H2P     12   // h2 padded stride (10 -> 12 so 3x float4 atomics work)

// ---------------- device scratch (static, no allocation) ----------------
__device__ __align__(16) float g_deg[N_NODES];
__device__ __align__(16) float g_dinv[N_NODES];
__device__ int   g_is64;
__device__ int   g_row[E_MAX];
__device__ int   g_col[E_MAX];
__device__ float g_norm[E_MAX];
__device__ __align__(16) float g_h1[N_NODES * HID];
__device__ __align__(16) float g_a1[N_NODES * HID];
__device__ __align__(16) float g_h2[N_NODES * H2P];
__device__ __align__(16) float g_g2[N_NODES * H2P];

// ---------------- helpers ----------------
__device__ __forceinline__ void red4(float* p, float a, float b, float c, float d) {
    asm volatile("red.global.add.v4.f32 [%0], {%1, %2, %3, %4};"
                 :: "l"(p), "f"(a), "f"(b), "f"(c), "f"(d) : "memory");
}

#define FFMA2(acc, a, b) \
    asm("fma.rn.f32x2 %0, %1, %2, %0;" : "+l"(acc) : "l"(a), "l"(b))

// ---------------- kernels ----------------
__global__ void k_zero() {
    int i = blockIdx.x * blockDim.x + threadIdx.x;
    int stride = gridDim.x * blockDim.x;
    float4 z = make_float4(0.f, 0.f, 0.f, 0.f);
    for (int j = i; j < N_NODES / 4; j += stride)        ((float4*)g_deg)[j] = z;
    for (int j = i; j < N_NODES * HID / 4; j += stride)  ((float4*)g_a1)[j]  = z;
    for (int j = i; j < N_NODES * H2P / 4; j += stride)  ((float4*)g_g2)[j]  = z;
}

// Detect whether edge_index is int64 or was downcast to int32 by the harness.
// int64 indices are all in [0, N). An int32 buffer read as int64 packs two
// indices (lo + hi<<32); hi != 0 with prob ~1 per element, so 256 in-range
// consecutive int64 reads <=> genuinely int64.
__global__ void k_detect(const void* ei) {
    if (blockIdx.x == 0 && threadIdx.x == 0) {
        const long long* p = (const long long*)ei;
        int ok = 1;
        for (int i = 0; i < 256; i++) {
            long long v = p[i];
            if (v < 0 || v >= N_NODES) { ok = 0; break; }
        }
        g_is64 = ok;
    }
}

// index conversion (either width) + weighted in-degree at targets
__global__ void k_prep(const void* __restrict__ eiv,
                       const float* __restrict__ ew, int E) {
    int e = blockIdx.x * blockDim.x + threadIdx.x;
    if (e >= E) return;
    int r, c;
    if (g_is64) {
        const long long* ei = (const long long*)eiv;
        r = (int)ei[e];
        c = (int)ei[E + e];
    } else {
        const int* ei = (const int*)eiv;
        r = ei[e];
        c = ei[E + e];
    }
    g_row[e] = r;
    g_col[e] = c;
    atomicAdd(&g_deg[c], ew[e]);
}

__global__ void k_dinv() {
    int n = blockIdx.x * blockDim.x + threadIdx.x;
    if (n < N_NODES) g_dinv[n] = rsqrtf(g_deg[n] + 1.0f);  // +1 = self loop weight
}

// h1 = x @ W1  (N x 300 @ 300 x 16), f32x2 packed FMA, smem-tiled
__global__ void __launch_bounds__(128) k_gemm1(const float* __restrict__ x,
                                               const float* __restrict__ W1) {
    __shared__ __align__(16) float w1s[F_INN * HID];   // 19200 B
    __shared__ __align__(16) float xs[128 * 36];       // 18432 B, pad 36
    int tid = threadIdx.x;
    for (int i = tid; i < F_INN * HID; i += 128) w1s[i] = W1[i];
    int node0 = blockIdx.x * 128;

    unsigned long long acc[8];
#pragma unroll
    for (int j = 0; j < 8; j++) acc[j] = 0ULL;

    for (int kc = 0; kc < F_INN; kc += 32) {
        int chunk = min(32, F_INN - kc);
        int cq = chunk >> 2;  // float4s per node: 8 or 3
        __syncthreads();
        for (int idx = tid; idx < 128 * cq; idx += 128) {
            int nd = idx / cq, q = idx - nd * cq;
            float4 v = make_float4(0.f, 0.f, 0.f, 0.f);
            if (node0 + nd < N_NODES)
                v = *(const float4*)&x[(node0 + nd) * F_INN + kc + q * 4];
            *(float4*)&xs[nd * 36 + q * 4] = v;
        }
        __syncthreads();

        if (chunk == 32) {
#pragma unroll
            for (int k = 0; k < 32; k++) {
                float xv = xs[tid * 36 + k];
                unsigned long long xx;
                asm("mov.b64 %0, {%1, %1};" : "=l"(xx) : "f"(xv));
                const ulonglong2* wr = (const ulonglong2*)&w1s[(kc + k) * HID];
                ulonglong2 w0 = wr[0], w1 = wr[1], w2 = wr[2], w3 = wr[3];
                FFMA2(acc[0], xx, w0.x); FFMA2(acc[1], xx, w0.y);
                FFMA2(acc[2], xx, w1.x); FFMA2(acc[3], xx, w1.y);
                FFMA2(acc[4], xx, w2.x); FFMA2(acc[5], xx, w2.y);
                FFMA2(acc[6], xx, w3.x); FFMA2(acc[7], xx, w3.y);
            }
        } else {
            for (int k = 0; k < chunk; k++) {
                float xv = xs[tid * 36 + k];
                unsigned long long xx;
                asm("mov.b64 %0, {%1, %1};" : "=l"(xx) : "f"(xv));
                const ulonglong2* wr = (const ulonglong2*)&w1s[(kc + k) * HID];
                ulonglong2 w0 = wr[0], w1 = wr[1], w2 = wr[2], w3 = wr[3];
                FFMA2(acc[0], xx, w0.x); FFMA2(acc[1], xx, w0.y);
                FFMA2(acc[2], xx, w1.x); FFMA2(acc[3], xx, w1.y);
                FFMA2(acc[4], xx, w2.x); FFMA2(acc[5], xx, w2.y);
                FFMA2(acc[6], xx, w3.x); FFMA2(acc[7], xx, w3.y);
            }
        }
    }

    int node = node0 + tid;
    if (node < N_NODES) {
        float o[16];
#pragma unroll
        for (int j = 0; j < 8; j++)
            asm("mov.b64 {%0, %1}, %2;" : "=f"(o[2 * j]), "=f"(o[2 * j + 1]) : "l"(acc[j]));
        float4* dst = (float4*)&g_h1[node * HID];
        dst[0] = make_float4(o[0], o[1], o[2], o[3]);
        dst[1] = make_float4(o[4], o[5], o[6], o[7]);
        dst[2] = make_float4(o[8], o[9], o[10], o[11]);
        dst[3] = make_float4(o[12], o[13], o[14], o[15]);
    }
}

// conv1 edge scatter: also computes + caches norm
__global__ void k_scatter1(const float* __restrict__ ew, int E) {
    int e = blockIdx.x * blockDim.x + threadIdx.x;
    if (e >= E) return;
    int r = g_row[e], c = g_col[e];
    float nv = g_dinv[r] * ew[e] * g_dinv[c];
    g_norm[e] = nv;
    const float4* hp = (const float4*)&g_h1[r * HID];
    float* dst = &g_a1[c * HID];
#pragma unroll
    for (int q = 0; q < 4; q++) {
        float4 h = hp[q];
        red4(dst + q * 4, h.x * nv, h.y * nv, h.z * nv, h.w * nv);
    }
}

// self-loop + bias + relu + (relu @ W2) -> h2 (padded to 12)
__global__ void k_node1(const float* __restrict__ b1, const float* __restrict__ W2) {
    __shared__ float w2s[HID * C_OUT];
    __shared__ float b1s[HID];
    int tid = threadIdx.x;
    for (int i = tid; i < HID * C_OUT; i += blockDim.x) w2s[i] = W2[i];
    if (tid < HID) b1s[tid] = b1[tid];
    __syncthreads();
    int n = blockIdx.x * blockDim.x + tid;
    if (n >= N_NODES) return;
    float di = g_dinv[n];
    float di2 = di * di;
    const float4* ap = (const float4*)&g_a1[n * HID];
    const float4* hp = (const float4*)&g_h1[n * HID];
    float v[HID];
#pragma unroll
    for (int q = 0; q < 4; q++) {
        float4 a = ap[q], h = hp[q];
        v[4 * q + 0] = fmaxf(a.x + h.x * di2 + b1s[4 * q + 0], 0.f);
        v[4 * q + 1] = fmaxf(a.y + h.y * di2 + b1s[4 * q + 1], 0.f);
        v[4 * q + 2] = fmaxf(a.z + h.z * di2 + b1s[4 * q + 2], 0.f);
        v[4 * q + 3] = fmaxf(a.w + h.w * di2 + b1s[4 * q + 3], 0.f);
    }
    float o[H2P];
#pragma unroll
    for (int j = 0; j < C_OUT; j++) {
        float s = 0.f;
#pragma unroll
        for (int k = 0; k < HID; k++) s += v[k] * w2s[k * C_OUT + j];
        o[j] = s;
    }
    o[10] = 0.f; o[11] = 0.f;
    float4* dst = (float4*)&g_h2[n * H2P];
    dst[0] = make_float4(o[0], o[1], o[2], o[3]);
    dst[1] = make_float4(o[4], o[5], o[6], o[7]);
    dst[2] = make_float4(o[8], o[9], o[10], o[11]);
}

// conv2 edge scatter (uses cached norm)
__global__ void k_scatter2(int E) {
    int e = blockIdx.x * blockDim.x + threadIdx.x;
    if (e >= E) return;
    int r = g_row[e], c = g_col[e];
    float nv = g_norm[e];
    const float4* hp = (const float4*)&g_h2[r * H2P];
    float* dst = &g_g2[c * H2P];
#pragma unroll
    for (int q = 0; q < 3; q++) {
        float4 h = hp[q];
        red4(dst + q * 4, h.x * nv, h.y * nv, h.z * nv, h.w * nv);
    }
}

// self-loop + b2 + log_softmax
__global__ void k_final(const float* __restrict__ b2, float* __restrict__ out) {
    int n = blockIdx.x * blockDim.x + threadIdx.x;
    if (n >= N_NODES) return;
    float di = g_dinv[n];
    float di2 = di * di;
    float t[C_OUT];
#pragma unroll
    for (int j = 0; j < C_OUT; j++)
        t[j] = g_g2[n * H2P + j] + g_h2[n * H2P + j] * di2 + __ldg(&b2[j]);
    float m = t[0];
#pragma unroll
    for (int j = 1; j < C_OUT; j++) m = fmaxf(m, t[j]);
    float s = 0.f;
#pragma unroll
    for (int j = 0; j < C_OUT; j++) s += expf(t[j] - m);
    float l = logf(s) + m;
#pragma unroll
    for (int j = 0; j < C_OUT; j++) out[n * C_OUT + j] = t[j] - l;
}

// ---------------- launcher ----------------
extern "C" void kernel_launch(void* const* d_in, const int* in_sizes, int n_in,
                              void* d_out, int out_size) {
    const float* x  = (const float*)d_in[0];
    const void*  ei = d_in[1];
    const float* ew = (const float*)d_in[2];
    const float* W1 = (const float*)d_in[3];
    const float* b1 = (const float*)d_in[4];
    const float* W2 = (const float*)d_in[5];
    const float* b2 = (const float*)d_in[6];
    float* out = (float*)d_out;
    int E = in_sizes[2];

    k_zero<<<2048, 256>>>();
    k_detect<<<1, 32>>>(ei);
    k_prep<<<(E + 255) / 256, 256>>>(ei, ew, E);
    k_dinv<<<(N_NODES + 255) / 256, 256>>>();
    k_gemm1<<<(N_NODES + 127) / 128, 128>>>(x, W1);
    k_scatter1<<<(E + 255) / 256, 256>>>(ew, E);
    k_node1<<<(N_NODES + 127) / 128, 128>>>(b1, W2);
    k_scatter2<<<(E + 255) / 256, 256>>>(E);
    k_final<<<(N_NODES + 255) / 256, 256>>>(b2, out);
}

// round 4
// speedup vs baseline: 1.1700x; 1.1700x over previous
#include <cuda_runtime.h>

#define N_NODES 100000
#define E_MAX   3200000
#define F_INN   300
#define HID     16
#define C_OUT   10
#define H2P     12
#define NBLK_SCAN 98   // ceil(100000/1024)

// ---------------- device scratch (static, no allocation) ----------------
__device__ __align__(16) float g_deg[N_NODES];
__device__ __align__(16) float g_dinv[N_NODES];
__device__ int   g_is64;
__device__ int   g_cnt[N_NODES];
__device__ int   g_start[N_NODES + 1];
__device__ int   g_pos[N_NODES];
__device__ int   g_bsum[NBLK_SCAN];
__device__ int   g_boff[NBLK_SCAN];
__device__ __align__(16) int2  g_edge[E_MAX];   // {row, norm-bits}, sorted by col
__device__ __align__(16) float g_h1[N_NODES * HID];
__device__ __align__(16) float g_a1[N_NODES * HID];
__device__ __align__(16) float g_h2[N_NODES * H2P];
__device__ __align__(16) float g_g2[N_NODES * H2P];

#define FFMA2(acc, a, b) \
    asm("fma.rn.f32x2 %0, %1, %2, %0;" : "+l"(acc) : "l"(a), "l"(b))

// ---------------- kernels ----------------
__global__ void k_zero() {
    int i = blockIdx.x * blockDim.x + threadIdx.x;
    if (i < N_NODES) { g_deg[i] = 0.f; g_cnt[i] = 0; }
}

// edge_index dtype detect: 1 warp, ballot. int32-viewed-as-int64 has hi word
// = next index, in [0,N) only if that index==0 (p=1e-5 each) -> 32 hits ~ never.
__global__ void k_detect(const void* ei) {
    const long long* p = (const long long*)ei;
    long long v = p[threadIdx.x];
    int ok = (v >= 0 && v < N_NODES);
    unsigned m = __ballot_sync(0xffffffffu, ok);
    if (threadIdx.x == 0) g_is64 = (m == 0xffffffffu);
}

// weighted in-degree + integer histogram at targets
__global__ void k_prep(const void* __restrict__ eiv,
                       const float* __restrict__ ew, int E) {
    int e = blockIdx.x * blockDim.x + threadIdx.x;
    if (e >= E) return;
    int c = g_is64 ? (int)((const long long*)eiv)[E + e]
                   : ((const int*)eiv)[E + e];
    atomicAdd(&g_deg[c], ew[e]);
    atomicAdd(&g_cnt[c], 1);
}

__global__ void k_dinv() {
    int n = blockIdx.x * blockDim.x + threadIdx.x;
    if (n < N_NODES) g_dinv[n] = rsqrtf(g_deg[n] + 1.0f);  // +1 = self loop
}

// ---- exclusive scan of g_cnt (3 small kernels) ----
__global__ void k_scanA() {
    __shared__ int wsum[32];
    int i = blockIdx.x * 1024 + threadIdx.x;
    int lane = threadIdx.x & 31, wid = threadIdx.x >> 5;
    int v = (i < N_NODES) ? g_cnt[i] : 0;
    int incl = v;
#pragma unroll
    for (int d = 1; d < 32; d <<= 1) {
        int t = __shfl_up_sync(0xffffffffu, incl, d);
        if (lane >= d) incl += t;
    }
    if (lane == 31) wsum[wid] = incl;
    __syncthreads();
    if (wid == 0) {
        int s = wsum[lane];
#pragma unroll
        for (int d = 1; d < 32; d <<= 1) {
            int t = __shfl_up_sync(0xffffffffu, s, d);
            if (lane >= d) s += t;
        }
        wsum[lane] = s;
    }
    __syncthreads();
    int woff = (wid > 0) ? wsum[wid - 1] : 0;
    if (i < N_NODES) g_start[i] = incl - v + woff;  // block-local exclusive
    if (threadIdx.x == 1023) g_bsum[blockIdx.x] = wsum[31];
}

__global__ void k_scanB() {
    __shared__ int sh[128];
    int t = threadIdx.x;
    int v = (t < NBLK_SCAN) ? g_bsum[t] : 0;
    sh[t] = v;
    __syncthreads();
    for (int d = 1; d < 128; d <<= 1) {
        int x = (t >= d) ? sh[t - d] : 0;
        __syncthreads();
        sh[t] += x;
        __syncthreads();
    }
    if (t < NBLK_SCAN) g_boff[t] = sh[t] - v;  // exclusive
}

__global__ void k_scanC(int E) {
    int i = blockIdx.x * 1024 + threadIdx.x;
    if (i < N_NODES) {
        int s = g_start[i] + g_boff[blockIdx.x];
        g_start[i] = s;
        g_pos[i] = s;
    }
    if (i == 0) g_start[N_NODES] = E;
}

// scatter edges into CSR order, packing {row, norm}
__global__ void k_reorder(const void* __restrict__ eiv,
                          const float* __restrict__ ew, int E) {
    int e = blockIdx.x * blockDim.x + threadIdx.x;
    if (e >= E) return;
    int r, c;
    if (g_is64) {
        const long long* ei = (const long long*)eiv;
        r = (int)ei[e]; c = (int)ei[E + e];
    } else {
        const int* ei = (const int*)eiv;
        r = ei[e]; c = ei[E + e];
    }
    float nv = g_dinv[r] * ew[e] * g_dinv[c];
    int p = atomicAdd(&g_pos[c], 1);
    g_edge[p] = make_int2(r, __float_as_int(nv));
}

// h1 = x @ W1  (N x 300 @ 300 x 16), f32x2 packed FMA, smem-tiled
__global__ void __launch_bounds__(128) k_gemm1(const float* __restrict__ x,
                                               const float* __restrict__ W1) {
    __shared__ __align__(16) float w1s[F_INN * HID];
    __shared__ __align__(16) float xs[128 * 36];
    int tid = threadIdx.x;
    for (int i = tid; i < F_INN * HID; i += 128) w1s[i] = W1[i];
    int node0 = blockIdx.x * 128;

    unsigned long long acc[8];
#pragma unroll
    for (int j = 0; j < 8; j++) acc[j] = 0ULL;

    for (int kc = 0; kc < F_INN; kc += 32) {
        int chunk = min(32, F_INN - kc);
        int cq = chunk >> 2;
        __syncthreads();
        for (int idx = tid; idx < 128 * cq; idx += 128) {
            int nd = idx / cq, q = idx - nd * cq;
            float4 v = make_float4(0.f, 0.f, 0.f, 0.f);
            if (node0 + nd < N_NODES)
                v = *(const float4*)&x[(node0 + nd) * F_INN + kc + q * 4];
            *(float4*)&xs[nd * 36 + q * 4] = v;
        }
        __syncthreads();

        for (int k = 0; k < chunk; k++) {
            float xv = xs[tid * 36 + k];
            unsigned long long xx;
            asm("mov.b64 %0, {%1, %1};" : "=l"(xx) : "f"(xv));
            const ulonglong2* wr = (const ulonglong2*)&w1s[(kc + k) * HID];
            ulonglong2 w0 = wr[0], w1 = wr[1], w2 = wr[2], w3 = wr[3];
            FFMA2(acc[0], xx, w0.x); FFMA2(acc[1], xx, w0.y);
            FFMA2(acc[2], xx, w1.x); FFMA2(acc[3], xx, w1.y);
            FFMA2(acc[4], xx, w2.x); FFMA2(acc[5], xx, w2.y);
            FFMA2(acc[6], xx, w3.x); FFMA2(acc[7], xx, w3.y);
        }
    }

    int node = node0 + tid;
    if (node < N_NODES) {
        float o[16];
#pragma unroll
        for (int j = 0; j < 8; j++)
            asm("mov.b64 {%0, %1}, %2;" : "=f"(o[2 * j]), "=f"(o[2 * j + 1]) : "l"(acc[j]));
        float4* dst = (float4*)&g_h1[node * HID];
        dst[0] = make_float4(o[0], o[1], o[2], o[3]);
        dst[1] = make_float4(o[4], o[5], o[6], o[7]);
        dst[2] = make_float4(o[8], o[9], o[10], o[11]);
        dst[3] = make_float4(o[12], o[13], o[14], o[15]);
    }
}

// conv1: warp per node, gather-only. 8 edges x 4 feature-lanes per iteration.
__global__ void __launch_bounds__(256) k_conv1() {
    int warp = (blockIdx.x * blockDim.x + threadIdx.x) >> 5;
    if (warp >= N_NODES) return;
    int lane = threadIdx.x & 31;
    int q = lane & 3, eg = lane >> 2;
    int s = g_start[warp], e = g_start[warp + 1];
    float4 acc = make_float4(0.f, 0.f, 0.f, 0.f);
#pragma unroll 2
    for (int idx = s + eg; idx < e; idx += 8) {
        int2 ed = g_edge[idx];                       // 4-lane broadcast
        float nv = __int_as_float(ed.y);
        float4 h = *(const float4*)&g_h1[ed.x * HID + q * 4];
        acc.x += h.x * nv; acc.y += h.y * nv;
        acc.z += h.z * nv; acc.w += h.w * nv;
    }
#pragma unroll
    for (int d = 4; d < 32; d <<= 1) {
        acc.x += __shfl_xor_sync(0xffffffffu, acc.x, d);
        acc.y += __shfl_xor_sync(0xffffffffu, acc.y, d);
        acc.z += __shfl_xor_sync(0xffffffffu, acc.z, d);
        acc.w += __shfl_xor_sync(0xffffffffu, acc.w, d);
    }
    if (lane < 4) *(float4*)&g_a1[warp * HID + lane * 4] = acc;
}

// self-loop + bias + relu + (relu @ W2) -> h2 (padded to 12)
__global__ void k_node1(const float* __restrict__ b1, const float* __restrict__ W2) {
    __shared__ float w2s[HID * C_OUT];
    __shared__ float b1s[HID];
    int tid = threadIdx.x;
    for (int i = tid; i < HID * C_OUT; i += blockDim.x) w2s[i] = W2[i];
    if (tid < HID) b1s[tid] = b1[tid];
    __syncthreads();
    int n = blockIdx.x * blockDim.x + tid;
    if (n >= N_NODES) return;
    float di = g_dinv[n];
    float di2 = di * di;
    const float4* ap = (const float4*)&g_a1[n * HID];
    const float4* hp = (const float4*)&g_h1[n * HID];
    float v[HID];
#pragma unroll
    for (int qq = 0; qq < 4; qq++) {
        float4 a = ap[qq], h = hp[qq];
        v[4 * qq + 0] = fmaxf(a.x + h.x * di2 + b1s[4 * qq + 0], 0.f);
        v[4 * qq + 1] = fmaxf(a.y + h.y * di2 + b1s[4 * qq + 1], 0.f);
        v[4 * qq + 2] = fmaxf(a.z + h.z * di2 + b1s[4 * qq + 2], 0.f);
        v[4 * qq + 3] = fmaxf(a.w + h.w * di2 + b1s[4 * qq + 3], 0.f);
    }
    float o[H2P];
#pragma unroll
    for (int j = 0; j < C_OUT; j++) {
        float ssum = 0.f;
#pragma unroll
        for (int k = 0; k < HID; k++) ssum += v[k] * w2s[k * C_OUT + j];
        o[j] = ssum;
    }
    o[10] = 0.f; o[11] = 0.f;
    float4* dst = (float4*)&g_h2[n * H2P];
    dst[0] = make_float4(o[0], o[1], o[2], o[3]);
    dst[1] = make_float4(o[4], o[5], o[6], o[7]);
    dst[2] = make_float4(o[8], o[9], o[10], o[11]);
}

// conv2: warp per node over h2 (12 floats, q<3 active)
__global__ void __launch_bounds__(256) k_conv2() {
    int warp = (blockIdx.x * blockDim.x + threadIdx.x) >> 5;
    if (warp >= N_NODES) return;
    int lane = threadIdx.x & 31;
    int q = lane & 3, eg = lane >> 2;
    int s = g_start[warp], e = g_start[warp + 1];
    float4 acc = make_float4(0.f, 0.f, 0.f, 0.f);
#pragma unroll 2
    for (int idx = s + eg; idx < e; idx += 8) {
        int2 ed = g_edge[idx];
        float nv = __int_as_float(ed.y);
        if (q < 3) {
            float4 h = *(const float4*)&g_h2[ed.x * H2P + q * 4];
            acc.x += h.x * nv; acc.y += h.y * nv;
            acc.z += h.z * nv; acc.w += h.w * nv;
        }
    }
#pragma unroll
    for (int d = 4; d < 32; d <<= 1) {
        acc.x += __shfl_xor_sync(0xffffffffu, acc.x, d);
        acc.y += __shfl_xor_sync(0xffffffffu, acc.y, d);
        acc.z += __shfl_xor_sync(0xffffffffu, acc.z, d);
        acc.w += __shfl_xor_sync(0xffffffffu, acc.w, d);
    }
    if (lane < 3) *(float4*)&g_g2[warp * H2P + lane * 4] = acc;
}

// self-loop + b2 + log_softmax
__global__ void k_final(const float* __restrict__ b2, float* __restrict__ out) {
    int n = blockIdx.x * blockDim.x + threadIdx.x;
    if (n >= N_NODES) return;
    float di = g_dinv[n];
    float di2 = di * di;
    float t[C_OUT];
#pragma unroll
    for (int j = 0; j < C_OUT; j++)
        t[j] = g_g2[n * H2P + j] + g_h2[n * H2P + j] * di2 + __ldg(&b2[j]);
    float m = t[0];
#pragma unroll
    for (int j = 1; j < C_OUT; j++) m = fmaxf(m, t[j]);
    float ssum = 0.f;
#pragma unroll
    for (int j = 0; j < C_OUT; j++) ssum += expf(t[j] - m);
    float l = logf(ssum) + m;
#pragma unroll
    for (int j = 0; j < C_OUT; j++) out[n * C_OUT + j] = t[j] - l;
}

// ---------------- launcher ----------------
extern "C" void kernel_launch(void* const* d_in, const int* in_sizes, int n_in,
                              void* d_out, int out_size) {
    const float* x  = (const float*)d_in[0];
    const void*  ei = d_in[1];
    const float* ew = (const float*)d_in[2];
    const float* W1 = (const float*)d_in[3];
    const float* b1 = (const float*)d_in[4];
    const float* W2 = (const float*)d_in[5];
    const float* b2 = (const float*)d_in[6];
    float* out = (float*)d_out;
    int E = in_sizes[2];

    k_zero<<<(N_NODES + 255) / 256, 256>>>();
    k_detect<<<1, 32>>>(ei);
    k_prep<<<(E + 255) / 256, 256>>>(ei, ew, E);
    k_dinv<<<(N_NODES + 255) / 256, 256>>>();
    k_scanA<<<NBLK_SCAN, 1024>>>();
    k_scanB<<<1, 128>>>();
    k_scanC<<<NBLK_SCAN, 1024>>>(E);
    k_reorder<<<(E + 255) / 256, 256>>>(ei, ew, E);
    k_gemm1<<<(N_NODES + 127) / 128, 128>>>(x, W1);
    k_conv1<<<(N_NODES * 32 + 255) / 256, 256>>>();
    k_node1<<<(N_NODES + 127) / 128, 128>>>(b1, W2);
    k_conv2<<<(N_NODES * 32 + 255) / 256, 256>>>();
    k_final<<<(N_NODES + 255) / 256, 256>>>(b2, out);
}

// round 6
// speedup vs baseline: 1.2956x; 1.1073x over previous
#include <cuda_runtime.h>

#define N_NODES 100000
#define E_MAX   3200000
#define F_INN   300
#define HID     16
#define C_OUT   10
#define H2P     12
#define NBLK_SCAN 98   // ceil(100000/1024)
#define DEG_MASK 0xFFFFFFFFFFULL   // low 40 bits: weighted degree, 2^-24 fixed point

// ---------------- device scratch (static, no allocation) ----------------
__device__ unsigned long long g_hist[N_NODES];  // count<<40 | fixedpoint(deg)
__device__ __align__(16) float g_dinv[N_NODES];
__device__ int   g_is64;
__device__ int   g_start[N_NODES + 1];
__device__ int   g_pos[N_NODES];
__device__ int   g_bsum[NBLK_SCAN];
__device__ __align__(16) int2  g_edge[E_MAX];   // {row, norm-bits}, sorted by col
__device__ __align__(16) float g_h1[N_NODES * HID];
__device__ __align__(16) float g_h2[N_NODES * H2P];

#define FFMA2(acc, a, b) \
    asm("fma.rn.f32x2 %0, %1, %2, %0;" : "+l"(acc) : "l"(a), "l"(b))

// ---------------- kernels ----------------
// zero histogram + dtype detect (warp 0 of block 0)
__global__ void k_init(const void* ei) {
    int i = blockIdx.x * blockDim.x + threadIdx.x;
    if (i < N_NODES) g_hist[i] = 0ULL;
    if (blockIdx.x == 0 && threadIdx.x < 32) {
        const long long* p = (const long long*)ei;
        long long v = p[threadIdx.x];
        int ok = (v >= 0 && v < N_NODES);
        unsigned m = __ballot_sync(0xffffffffu, ok);
        if (threadIdx.x == 0) g_is64 = (m == 0xffffffffu);
    }
}

// one fused 64-bit atomic: count + fixed-point weighted in-degree
__global__ void k_prep(const void* __restrict__ eiv,
                       const float* __restrict__ ew, int E) {
    int e = blockIdx.x * blockDim.x + threadIdx.x;
    if (e >= E) return;
    int c = g_is64 ? (int)((const long long*)eiv)[E + e]
                   : ((const int*)eiv)[E + e];
    unsigned long long q = __float2ull_rn(ew[e] * 16777216.0f);
    atomicAdd(&g_hist[c], (1ULL << 40) | q);
}

// block-local exclusive scan of counts + dinv computation
__global__ void k_scanA() {
    __shared__ int wsum[32];
    int i = blockIdx.x * 1024 + threadIdx.x;
    int lane = threadIdx.x & 31, wid = threadIdx.x >> 5;
    int v = 0;
    if (i < N_NODES) {
        unsigned long long hv = g_hist[i];
        v = (int)(hv >> 40);
        float deg = (float)((double)(hv & DEG_MASK) * (1.0 / 16777216.0));
        g_dinv[i] = rsqrtf(deg + 1.0f);   // +1 = self loop weight
    }
    int incl = v;
#pragma unroll
    for (int d = 1; d < 32; d <<= 1) {
        int t = __shfl_up_sync(0xffffffffu, incl, d);
        if (lane >= d) incl += t;
    }
    if (lane == 31) wsum[wid] = incl;
    __syncthreads();
    if (wid == 0) {
        int s = wsum[lane];
#pragma unroll
        for (int d = 1; d < 32; d <<= 1) {
            int t = __shfl_up_sync(0xffffffffu, s, d);
            if (lane >= d) s += t;
        }
        wsum[lane] = s;
    }
    __syncthreads();
    int woff = (wid > 0) ? wsum[wid - 1] : 0;
    if (i < N_NODES) g_start[i] = incl - v + woff;
    if (threadIdx.x == 1023) g_bsum[blockIdx.x] = wsum[31];
}

// fused: scan of block sums (per-block, warp 0) + apply offsets
__global__ void k_scanC(int E) {
    __shared__ int sh[128];
    int t = threadIdx.x;
    if (t < 128) sh[t] = (t < NBLK_SCAN) ? g_bsum[t] : 0;
    __syncthreads();
    if (t < 32) {
        int e0 = sh[4 * t], e1 = sh[4 * t + 1], e2 = sh[4 * t + 2], e3 = sh[4 * t + 3];
        int s = e0 + e1 + e2 + e3;
        int incl = s;
#pragma unroll
        for (int d = 1; d < 32; d <<= 1) {
            int x = __shfl_up_sync(0xffffffffu, incl, d);
            if (t >= d) incl += x;
        }
        int base = incl - s;  // exclusive prefix of this 4-group
        sh[4 * t] = base;
        sh[4 * t + 1] = base + e0;
        sh[4 * t + 2] = base + e0 + e1;
        sh[4 * t + 3] = base + e0 + e1 + e2;
    }
    __syncthreads();
    int i = blockIdx.x * 1024 + t;
    if (i < N_NODES) {
        int s = g_start[i] + sh[blockIdx.x];
        g_start[i] = s;
        g_pos[i] = s;
    }
    if (i == 0) g_start[N_NODES] = E;
}

// scatter edges into CSR order, packing {row, norm}
__global__ void k_reorder(const void* __restrict__ eiv,
                          const float* __restrict__ ew, int E) {
    int e = blockIdx.x * blockDim.x + threadIdx.x;
    if (e >= E) return;
    int r, c;
    if (g_is64) {
        const long long* ei = (const long long*)eiv;
        r = (int)ei[e]; c = (int)ei[E + e];
    } else {
        const int* ei = (const int*)eiv;
        r = ei[e]; c = ei[E + e];
    }
    float nv = g_dinv[r] * ew[e] * g_dinv[c];
    int p = atomicAdd(&g_pos[c], 1);
    g_edge[p] = make_int2(r, __float_as_int(nv));
}

// h1 = x @ W1  (N x 300 @ 300 x 16), f32x2 packed FMA, smem-tiled
__global__ void __launch_bounds__(128) k_gemm1(const float* __restrict__ x,
                                               const float* __restrict__ W1) {
    __shared__ __align__(16) float w1s[F_INN * HID];
    __shared__ __align__(16) float xs[128 * 36];
    int tid = threadIdx.x;
    for (int i = tid; i < F_INN * HID; i += 128) w1s[i] = W1[i];
    int node0 = blockIdx.x * 128;

    unsigned long long acc[8];
#pragma unroll
    for (int j = 0; j < 8; j++) acc[j] = 0ULL;

    for (int kc = 0; kc < F_INN; kc += 32) {
        int chunk = min(32, F_INN - kc);
        int cq = chunk >> 2;
        __syncthreads();
        for (int idx = tid; idx < 128 * cq; idx += 128) {
            int nd = idx / cq, q = idx - nd * cq;
            float4 v = make_float4(0.f, 0.f, 0.f, 0.f);
            if (node0 + nd < N_NODES)
                v = *(const float4*)&x[(node0 + nd) * F_INN + kc + q * 4];
            *(float4*)&xs[nd * 36 + q * 4] = v;
        }
        __syncthreads();

        for (int k = 0; k < chunk; k++) {
            float xv = xs[tid * 36 + k];
            unsigned long long xx;
            asm("mov.b64 %0, {%1, %1};" : "=l"(xx) : "f"(xv));
            const ulonglong2* wr = (const ulonglong2*)&w1s[(kc + k) * HID];
            ulonglong2 w0 = wr[0], w1 = wr[1], w2 = wr[2], w3 = wr[3];
            FFMA2(acc[0], xx, w0.x); FFMA2(acc[1], xx, w0.y);
            FFMA2(acc[2], xx, w1.x); FFMA2(acc[3], xx, w1.y);
            FFMA2(acc[4], xx, w2.x); FFMA2(acc[5], xx, w2.y);
            FFMA2(acc[6], xx, w3.x); FFMA2(acc[7], xx, w3.y);
        }
    }

    int node = node0 + tid;
    if (node < N_NODES) {
        float o[16];
#pragma unroll
        for (int j = 0; j < 8; j++)
            asm("mov.b64 {%0, %1}, %2;" : "=f"(o[2 * j]), "=f"(o[2 * j + 1]) : "l"(acc[j]));
        float4* dst = (float4*)&g_h1[node * HID];
        dst[0] = make_float4(o[0], o[1], o[2], o[3]);
        dst[1] = make_float4(o[4], o[5], o[6], o[7]);
        dst[2] = make_float4(o[8], o[9], o[10], o[11]);
        dst[3] = make_float4(o[12], o[13], o[14], o[15]);
    }
}

// conv1 + node1 fused: warp per node gather, then bias+relu+W2 in-warp -> h2
__global__ void __launch_bounds__(256) k_conv1(const float* __restrict__ b1,
                                               const float* __restrict__ W2) {
    int warp = (blockIdx.x * blockDim.x + threadIdx.x) >> 5;
    if (warp >= N_NODES) return;
    int lane = threadIdx.x & 31;
    int q = lane & 3, eg = lane >> 2;
    int s = g_start[warp], e = g_start[warp + 1];
    float4 acc = make_float4(0.f, 0.f, 0.f, 0.f);
#pragma unroll 2
    for (int idx = s + eg; idx < e; idx += 8) {
        int2 ed = g_edge[idx];
        float nv = __int_as_float(ed.y);
        float4 h = *(const float4*)&g_h1[ed.x * HID + q * 4];
        acc.x += h.x * nv; acc.y += h.y * nv;
        acc.z += h.z * nv; acc.w += h.w * nv;
    }
#pragma unroll
    for (int d = 4; d < 32; d <<= 1) {
        acc.x += __shfl_xor_sync(0xffffffffu, acc.x, d);
        acc.y += __shfl_xor_sync(0xffffffffu, acc.y, d);
        acc.z += __shfl_xor_sync(0xffffffffu, acc.z, d);
        acc.w += __shfl_xor_sync(0xffffffffu, acc.w, d);
    }
    // fused node1: self-loop + bias + relu
    float di = g_dinv[warp];
    float di2 = di * di;
    float4 h1q = *(const float4*)&g_h1[warp * HID + q * 4];
    float4 bq  = *(const float4*)&b1[q * 4];
    float4 v;
    v.x = fmaxf(acc.x + h1q.x * di2 + bq.x, 0.f);
    v.y = fmaxf(acc.y + h1q.y * di2 + bq.y, 0.f);
    v.z = fmaxf(acc.z + h1q.z * di2 + bq.z, 0.f);
    v.w = fmaxf(acc.w + h1q.w * di2 + bq.w, 0.f);
    // broadcast the 16-dim relu vector to all lanes (constant-indexed -> regs)
    float vv[16];
#pragma unroll
    for (int c = 0; c < 4; c++) {
        vv[4 * c + 0] = __shfl_sync(0xffffffffu, v.x, c);
        vv[4 * c + 1] = __shfl_sync(0xffffffffu, v.y, c);
        vv[4 * c + 2] = __shfl_sync(0xffffffffu, v.z, c);
        vv[4 * c + 3] = __shfl_sync(0xffffffffu, v.w, c);
    }
    if (lane < H2P) {
        float o = 0.f;
        if (lane < C_OUT) {
#pragma unroll
            for (int k = 0; k < HID; k++)
                o += vv[k] * __ldg(&W2[k * C_OUT + lane]);
        }
        g_h2[warp * H2P + lane] = o;
    }
}

// conv2 + final fused: gather, self-loop + b2 + log_softmax in-warp -> out
__global__ void __launch_bounds__(256) k_conv2(const float* __restrict__ b2,
                                               float* __restrict__ out) {
    int warp = (blockIdx.x * blockDim.x + threadIdx.x) >> 5;
    if (warp >= N_NODES) return;
    int lane = threadIdx.x & 31;
    int q = lane & 3, eg = lane >> 2;
    int s = g_start[warp], e = g_start[warp + 1];
    float4 acc = make_float4(0.f, 0.f, 0.f, 0.f);
#pragma unroll 2
    for (int idx = s + eg; idx < e; idx += 8) {
        int2 ed = g_edge[idx];
        float nv = __int_as_float(ed.y);
        if (q < 3) {
            float4 h = *(const float4*)&g_h2[ed.x * H2P + q * 4];
            acc.x += h.x * nv; acc.y += h.y * nv;
            acc.z += h.z * nv; acc.w += h.w * nv;
        }
    }
#pragma unroll
    for (int d = 4; d < 32; d <<= 1) {
        acc.x += __shfl_xor_sync(0xffffffffu, acc.x, d);
        acc.y += __shfl_xor_sync(0xffffffffu, acc.y, d);
        acc.z += __shfl_xor_sync(0xffffffffu, acc.z, d);
        acc.w += __shfl_xor_sync(0xffffffffu, acc.w, d);
    }
    // fused final: self-loop + b2 + log_softmax
    float di = g_dinv[warp];
    float di2 = di * di;
    float4 tq = make_float4(0.f, 0.f, 0.f, 0.f);
    if (q < 3) {
        float4 h2q = *(const float4*)&g_h2[warp * H2P + q * 4];
        tq.x = acc.x + h2q.x * di2;
        tq.y = acc.y + h2q.y * di2;
        tq.z = acc.z + h2q.z * di2;
        tq.w = acc.w + h2q.w * di2;
    }
    // lane j takes component (j&3) of quad from lane (j>>2)
    int src = lane >> 2;
    float a0 = __shfl_sync(0xffffffffu, tq.x, src);
    float a1 = __shfl_sync(0xffffffffu, tq.y, src);
    float a2 = __shfl_sync(0xffffffffu, tq.z, src);
    float a3 = __shfl_sync(0xffffffffu, tq.w, src);
    float tj = (q == 0) ? a0 : (q == 1) ? a1 : (q == 2) ? a2 : a3;
    tj = (lane < C_OUT) ? tj + __ldg(&b2[lane]) : -3.4e38f;
    float m = tj;
#pragma unroll
    for (int d = 16; d >= 1; d >>= 1) m = fmaxf(m, __shfl_xor_sync(0xffffffffu, m, d));
    float ex = (lane < C_OUT) ? expf(tj - m) : 0.f;
    float ssum = ex;
#pragma unroll
    for (int d = 16; d >= 1; d >>= 1) ssum += __shfl_xor_sync(0xffffffffu, ssum, d);
    float l = logf(ssum) + m;
    if (lane < C_OUT) out[warp * C_OUT + lane] = tj - l;
}

// ---------------- launcher ----------------
extern "C" void kernel_launch(void* const* d_in, const int* in_sizes, int n_in,
                              void* d_out, int out_size) {
    const float* x  = (const float*)d_in[0];
    const void*  ei = d_in[1];
    const float* ew = (const float*)d_in[2];
    const float* W1 = (const float*)d_in[3];
    const float* b1 = (const float*)d_in[4];
    const float* W2 = (const float*)d_in[5];
    const float* b2 = (const float*)d_in[6];
    float* out = (float*)d_out;
    int E = in_sizes[2];

    k_init<<<(N_NODES + 255) / 256, 256>>>(ei);
    k_prep<<<(E + 255) / 256, 256>>>(ei, ew, E);
    k_scanA<<<NBLK_SCAN, 1024>>>();
    k_scanC<<<NBLK_SCAN, 1024>>>(E);
    k_reorder<<<(E + 255) / 256, 256>>>(ei, ew, E);
    k_gemm1<<<(N_NODES + 127) / 128, 128>>>(x, W1);
    k_conv1<<<(N_NODES * 32 + 255) / 256, 256>>>(b1, W2);
    k_conv2<<<(N_NODES * 32 + 255) / 256, 256>>>(b2, out);
}